// round 16
// baseline (speedup 1.0000x reference)
#include <cuda_runtime.h>
#include <cuda_fp16.h>
#include <math.h>
#include <stdint.h>

// Problem constants (fixed by the reference)
#define S_LEN   2048
#define BATCH   2
#define DMODEL  1024
#define NHEAD   16
#define DHEAD   64
#define MROWS   (S_LEN * BATCH)
#define NELEM   (S_LEN * BATCH * DMODEL)   // 4M

// Scratch (no allocation allowed)
__device__ float  g_q[NELEM];                       // Q projected, f32
__device__ __align__(16) __half g_kh[NELEM];        // K projected, fp16
__device__ __align__(16) __half g_vt[NELEM];        // V projected, fp16 TRANSPOSED [(h,b)][d][s]
__device__ __align__(16) __half g_ahi[NELEM];       // attention out hi (fp16)
__device__ __align__(16) __half g_alo[NELEM];       // attention out lo (fp16)
// fp16 weights
__device__ __align__(16) __half g_wq[DMODEL * DMODEL];
__device__ __align__(16) __half g_wk[DMODEL * DMODEL];
__device__ __align__(16) __half g_wv[DMODEL * DMODEL];
__device__ __align__(16) __half g_wo[DMODEL * DMODEL];
// fp16 hi/lo split activations
__device__ __align__(16) __half g_xhi[3 * NELEM];
__device__ __align__(16) __half g_xlo[3 * NELEM];

// ---------------------------------------------------------------------------
// Helpers
// ---------------------------------------------------------------------------
// fp16 m16n8k16, fp32 accumulate
__device__ __forceinline__ void mma16(float c[4], const uint32_t a[4],
                                      const uint32_t b[2]) {
    asm volatile(
        "mma.sync.aligned.m16n8k16.row.col.f32.f16.f16.f32 "
        "{%0,%1,%2,%3}, {%4,%5,%6,%7}, {%8,%9}, {%0,%1,%2,%3};\n"
        : "+f"(c[0]), "+f"(c[1]), "+f"(c[2]), "+f"(c[3])
        : "r"(a[0]), "r"(a[1]), "r"(a[2]), "r"(a[3]),
          "r"(b[0]), "r"(b[1]));
}

__device__ __forceinline__ void cp_async16(uint32_t smem_addr, const void* gptr) {
    asm volatile("cp.async.cg.shared.global [%0], [%1], 16;\n"
                 :: "r"(smem_addr), "l"(gptr));
}
__device__ __forceinline__ void cp_commit() {
    asm volatile("cp.async.commit_group;\n");
}
__device__ __forceinline__ void cp_wait1() {
    asm volatile("cp.async.wait_group 1;\n");
}
__device__ __forceinline__ uint32_t smem_u32(const void* p) {
    return (uint32_t)__cvta_generic_to_shared(p);
}

__device__ __forceinline__ uint32_t pack2h(__half a, __half b) {
    return (uint32_t)__half_as_ushort(a) | ((uint32_t)__half_as_ushort(b) << 16);
}

// fp16 hi/lo split of two floats -> packed half2 hi and lo
__device__ __forceinline__ void split_pack_h(float x0, float x1,
                                             uint32_t& hi, uint32_t& lo) {
    __half h0 = __float2half_rn(x0);
    __half h1 = __float2half_rn(x1);
    __half l0 = __float2half_rn(x0 - __half2float(h0));
    __half l1 = __float2half_rn(x1 - __half2float(h1));
    hi = pack2h(h0, h1);
    lo = pack2h(l0, l1);
}

// ---------------------------------------------------------------------------
// Weight pre-conversion to fp16 (4 matrices, one launch)
// ---------------------------------------------------------------------------
struct RoundArgs { const float* w[4]; __half* o[4]; };

__global__ void __launch_bounds__(256)
round_w_kernel(RoundArgs a)
{
    const int z = blockIdx.z;
    const int i = (blockIdx.x * 256 + threadIdx.x) * 4;
    float4 v = *(const float4*)(a.w[z] + i);
    uint2 h;
    h.x = pack2h(__float2half_rn(v.x), __float2half_rn(v.y));
    h.y = pack2h(__float2half_rn(v.z), __float2half_rn(v.w));
    *(uint2*)(a.o[z] + i) = h;
}

// Activation pre-split to fp16 hi/lo (3 tensors, one launch)
struct SplitArgs { const float* x[3]; __half* hi[3]; __half* lo[3]; };

__global__ void __launch_bounds__(256)
split_x_kernel(SplitArgs a)
{
    const int z = blockIdx.z;
    const int i = (blockIdx.x * 256 + threadIdx.x) * 4;
    float4 v = *(const float4*)(a.x[z] + i);
    uint2 h, l;
    split_pack_h(v.x, v.y, h.x, l.x);
    split_pack_h(v.z, v.w, h.y, l.y);
    *(uint2*)(a.hi[z] + i) = h;
    *(uint2*)(a.lo[z] + i) = l;
}

// ---------------------------------------------------------------------------
// fp16 projection GEMM: Y = (Xhi+Xlo) @ W^T + bias, 2-pass k16.
// 3-stage cp.async pipeline, ONE barrier per k-iter.
// MODE: 0 = f32 out, 2 = fp16 out, 3 = fp16 TRANSPOSED out (for V).
// ---------------------------------------------------------------------------
#define GROWB 80
#define G_TILE_B (128 * GROWB)         // 10240
#define G_SMEM_B (9 * G_TILE_B)        // 92160 (Ahi[3] Alo[3] B[3])

template<int MODE>
__global__ void __launch_bounds__(256, 2)
gemm_fp16_kernel(const __half* __restrict__ Xhi, const __half* __restrict__ Xlo,
                 const __half* __restrict__ W, const float* __restrict__ bias,
                 void* __restrict__ Yv, int M, int N, int K)
{
    extern __shared__ char smc[];
    const int tid  = threadIdx.x;
    const int lane = tid & 31;
    const int w    = tid >> 5;
    const int wm   = w >> 2;
    const int wn   = w & 3;
    const int m0   = blockIdx.y * 128;
    const int n0   = blockIdx.x * 128;
    const int g    = lane >> 2;
    const int tg   = lane & 3;

    float c[4][4][4] = {};
    const uint32_t sbase = smem_u32(smc);

    auto issue_tile = [&](int k0, int buf) {
        #pragma unroll
        for (int i = 0; i < 2; i++) {
            const int ch  = i * 256 + tid;
            const int row = ch >> 2;
            const int seg = ch & 3;
            const uint32_t soff = (uint32_t)(row * GROWB + seg * 16);
            const size_t gx = (size_t)(m0 + row) * K + k0 + seg * 8;
            cp_async16(sbase + (uint32_t)buf * G_TILE_B + soff,  Xhi + gx);
            cp_async16(sbase + (3u + buf) * G_TILE_B + soff,     Xlo + gx);
            cp_async16(sbase + (6u + buf) * G_TILE_B + soff,
                       W + (size_t)(n0 + row) * K + k0 + seg * 8);
        }
    };

    issue_tile(0, 0);  cp_commit();
    issue_tile(32, 1); cp_commit();

    const int NT = K / 32;
    for (int kt = 0; kt < NT; kt++) {
        cp_wait1();              // tile kt complete (2 groups were outstanding)
        __syncthreads();         // all warps: tile kt visible; iter kt-1 reads done
        if (kt + 2 < NT) issue_tile((kt + 2) * 32, (kt + 2) % 3);
        cp_commit();             // commit every iter (possibly empty group)

        const int bf = kt % 3;
        const char* Ah = smc + bf * G_TILE_B + (wm * 64) * GROWB;
        const char* Al = smc + (3 + bf) * G_TILE_B + (wm * 64) * GROWB;
        const char* Bt = smc + (6 + bf) * G_TILE_B + (wn * 32) * GROWB;

        #pragma unroll
        for (int ks = 0; ks < 2; ks++) {
            const int kb = ks * 32 + tg * 4;
            uint32_t ahi[4][4], alo[4][4];
            #pragma unroll
            for (int mt = 0; mt < 4; mt++) {
                const char* ph = Ah + (mt * 16 + g) * GROWB + kb;
                const char* pl = Al + (mt * 16 + g) * GROWB + kb;
                ahi[mt][0] = *(const uint32_t*)(ph);
                ahi[mt][1] = *(const uint32_t*)(ph + 8 * GROWB);
                ahi[mt][2] = *(const uint32_t*)(ph + 16);
                ahi[mt][3] = *(const uint32_t*)(ph + 8 * GROWB + 16);
                alo[mt][0] = *(const uint32_t*)(pl);
                alo[mt][1] = *(const uint32_t*)(pl + 8 * GROWB);
                alo[mt][2] = *(const uint32_t*)(pl + 16);
                alo[mt][3] = *(const uint32_t*)(pl + 8 * GROWB + 16);
            }
            uint32_t bh[4][2];
            #pragma unroll
            for (int nt = 0; nt < 4; nt++) {
                const char* pb = Bt + (nt * 8 + g) * GROWB + kb;
                bh[nt][0] = *(const uint32_t*)(pb);
                bh[nt][1] = *(const uint32_t*)(pb + 16);
            }
            #pragma unroll
            for (int mt = 0; mt < 4; mt++)
                #pragma unroll
                for (int nt = 0; nt < 4; nt++) {
                    mma16(c[mt][nt], ahi[mt], bh[nt]);
                    mma16(c[mt][nt], alo[mt], bh[nt]);
                }
        }
    }

    #pragma unroll
    for (int mt = 0; mt < 4; mt++) {
        const int r0 = m0 + wm * 64 + mt * 16 + g;
        #pragma unroll
        for (int nt = 0; nt < 4; nt++) {
            const int cb = n0 + wn * 32 + nt * 8 + tg * 2;
            float2 bv = *(const float2*)(bias + cb);
            float2 v0, v1;
            v0.x = c[mt][nt][0] + bv.x; v0.y = c[mt][nt][1] + bv.y;
            v1.x = c[mt][nt][2] + bv.x; v1.y = c[mt][nt][3] + bv.y;
            if (MODE == 0) {
                *(float2*)((float*)Yv + (size_t)r0 * N + cb)       = v0;
                *(float2*)((float*)Yv + (size_t)(r0 + 8) * N + cb) = v1;
            } else if (MODE == 2) {
                uint32_t h0 = pack2h(__float2half_rn(v0.x), __float2half_rn(v0.y));
                uint32_t h1 = pack2h(__float2half_rn(v1.x), __float2half_rn(v1.y));
                *(uint32_t*)((__half*)Yv + (size_t)r0 * N + cb)       = h0;
                *(uint32_t*)((__half*)Yv + (size_t)(r0 + 8) * N + cb) = h1;
            } else {
                // MODE 3: transposed fp16 V:  Vt[(h*2+b)*64 + d][s]
                auto st = [&](int r, int cc, float v) {
                    const int s  = r >> 1;
                    const int bb = r & 1;
                    const int hh = cc >> 6;
                    const int d  = cc & 63;
                    ((__half*)Yv)[((size_t)((hh * 2 + bb) * 64 + d)) * S_LEN + s]
                        = __float2half_rn(v);
                };
                st(r0,     cb,     v0.x); st(r0,     cb + 1, v0.y);
                st(r0 + 8, cb,     v1.x); st(r0 + 8, cb + 1, v1.y);
            }
        }
    }
}

// ---------------------------------------------------------------------------
// Flash attention v6: all-fp16 tensor path, register-resident P (R15 proven),
// 3-stage K/V cp.async pipeline, ONE barrier per key-tile.
// ---------------------------------------------------------------------------
#define KROWB 144                       // K tile row: 64 halves + pad
#define A_KT  (128 * KROWB)             // 18432
#define VROWB 272                       // Vt tile row: 128 keys (fp16) + pad
#define VSTRH 136                       // Vt row stride in halves
#define A_VT  (64 * VROWB)              // 17408
#define A_K(buf) ((buf) * A_KT)
#define A_V(buf) (3 * A_KT + (buf) * A_VT)
#define A_TOTAL  (3 * A_KT + 3 * A_VT)  // 107520 (Q staged in same region first)

__global__ void __launch_bounds__(256)
attn_tc_kernel(const float* __restrict__ Q, const __half* __restrict__ Kp,
               const __half* __restrict__ Vtg,
               __half* __restrict__ Ohi, __half* __restrict__ Olo)
{
    extern __shared__ char smc[];
    const int tid  = threadIdx.x;
    const int lane = tid & 31;
    const int w    = tid >> 5;
    const int g    = lane >> 2;
    const int tg   = lane & 3;

    const int qblk = blockIdx.x;
    const int hb   = blockIdx.y;
    const int h    = hb >> 1;
    const int b    = hb & 1;
    const int hoff = h * DHEAD;

    const uint32_t sbase = smem_u32(smc);
    const __half* Vtp = Vtg + (size_t)(h * 2 + b) * 64 * S_LEN;

    auto gidx = [&](int row) -> size_t {
        return ((size_t)row * BATCH + b) * DMODEL + hoff;
    };

    // stage Q tile (128 x 64 f32) into smem (region reused by K/V after)
    {
        float* Qst = (float*)smc;
        #pragma unroll
        for (int i = 0; i < 8; i++) {
            const int ch  = i * 256 + tid;
            const int row = ch >> 4;
            const int seg = ch & 15;
            float4 v = *(const float4*)(Q + gidx(qblk * 128 + row) + seg * 4);
            *(float4*)&Qst[row * 132 + seg * 4] = v;
        }
    }
    __syncthreads();

    // persistent fp16 hi/lo Q fragments (4 k16-steps)
    uint32_t qhi[4][4], qlo[4][4];
    {
        const float* Qs = (const float*)smc + (w * 16) * 132;
        #pragma unroll
        for (int ks = 0; ks < 4; ks++) {
            const int kk = ks * 16;
            float2 q00 = *(const float2*)&Qs[g * 132 + kk + 2 * tg];
            float2 q10 = *(const float2*)&Qs[(g + 8) * 132 + kk + 2 * tg];
            float2 q01 = *(const float2*)&Qs[g * 132 + kk + 2 * tg + 8];
            float2 q11 = *(const float2*)&Qs[(g + 8) * 132 + kk + 2 * tg + 8];
            split_pack_h(q00.x, q00.y, qhi[ks][0], qlo[ks][0]);
            split_pack_h(q10.x, q10.y, qhi[ks][1], qlo[ks][1]);
            split_pack_h(q01.x, q01.y, qhi[ks][2], qlo[ks][2]);
            split_pack_h(q11.x, q11.y, qhi[ks][3], qlo[ks][3]);
        }
    }
    __syncthreads();   // Q staging fully consumed; K/V may overwrite

    // K (fp16, key-major) + Vt (fp16, dhead-major) tile loads
    auto issue_kv = [&](int kb, int buf) {
        #pragma unroll
        for (int i = 0; i < 4; i++) {            // K: 128 rows x 8 segs
            const int ch  = i * 256 + tid;
            const int row = ch >> 3;
            const int seg = ch & 7;
            cp_async16(sbase + (uint32_t)(A_K(buf) + row * KROWB + seg * 16),
                       Kp + gidx(kb + row) + seg * 8);
        }
        #pragma unroll
        for (int i = 0; i < 4; i++) {            // Vt: 64 rows x 16 segs
            const int ch  = i * 256 + tid;
            const int row = ch >> 4;             // 0..63 (dhead)
            const int seg = ch & 15;
            cp_async16(sbase + (uint32_t)(A_V(buf) + row * VROWB + seg * 16),
                       Vtp + (size_t)row * S_LEN + kb + seg * 8);
        }
    };

    issue_kv(0, 0);   cp_commit();
    issue_kv(128, 1); cp_commit();

    float o[8][4] = {};
    float mrow0 = -1e30f, mrow1 = -1e30f;
    float lrow0 = 0.0f,   lrow1 = 0.0f;
    const float scale = 0.125f;

    const int NKT = S_LEN / 128;   // 16 tiles
    for (int kt = 0; kt < NKT; kt++) {
        cp_wait1();              // tile kt complete
        __syncthreads();         // visible to all; iter kt-1 reads done
        if (kt + 2 < NKT) issue_kv((kt + 2) * 128, (kt + 2) % 3);
        cp_commit();             // commit every iter

        const int bf = kt % 3;
        const char* Kt = smc + A_K(bf);
        const __half* Vt = (const __half*)(smc + A_V(bf));

        // ---- QK^T over 128 keys: fp16 k16, 2-pass on Q split ----
        float s[16][4] = {};
        #pragma unroll
        for (int ks = 0; ks < 4; ks++) {
            const int kb = ks * 32 + tg * 4;
            #pragma unroll
            for (int nt = 0; nt < 16; nt++) {
                const char* pk = Kt + (nt * 8 + g) * KROWB + kb;
                uint32_t bh[2];
                bh[0] = *(const uint32_t*)(pk);
                bh[1] = *(const uint32_t*)(pk + 16);
                mma16(s[nt], qhi[ks], bh);
                mma16(s[nt], qlo[ks], bh);
            }
        }

        // ---- online softmax (R10 numerics, unchanged) ----
        float mx0 = -1e30f, mx1 = -1e30f;
        #pragma unroll
        for (int nt = 0; nt < 16; nt++) {
            s[nt][0] *= scale; s[nt][1] *= scale;
            s[nt][2] *= scale; s[nt][3] *= scale;
            mx0 = fmaxf(mx0, fmaxf(s[nt][0], s[nt][1]));
            mx1 = fmaxf(mx1, fmaxf(s[nt][2], s[nt][3]));
        }
        mx0 = fmaxf(mx0, __shfl_xor_sync(0xffffffffu, mx0, 1));
        mx0 = fmaxf(mx0, __shfl_xor_sync(0xffffffffu, mx0, 2));
        mx1 = fmaxf(mx1, __shfl_xor_sync(0xffffffffu, mx1, 1));
        mx1 = fmaxf(mx1, __shfl_xor_sync(0xffffffffu, mx1, 2));

        const float mn0 = fmaxf(mrow0, mx0);
        const float mn1 = fmaxf(mrow1, mx1);
        const float corr0 = __expf(mrow0 - mn0);
        const float corr1 = __expf(mrow1 - mn1);
        mrow0 = mn0; mrow1 = mn1;

        float sum0 = 0.0f, sum1 = 0.0f;
        #pragma unroll
        for (int nt = 0; nt < 16; nt++) {
            s[nt][0] = __expf(s[nt][0] - mn0);
            s[nt][1] = __expf(s[nt][1] - mn0);
            s[nt][2] = __expf(s[nt][2] - mn1);
            s[nt][3] = __expf(s[nt][3] - mn1);
            sum0 += s[nt][0] + s[nt][1];
            sum1 += s[nt][2] + s[nt][3];
        }
        sum0 += __shfl_xor_sync(0xffffffffu, sum0, 1);
        sum0 += __shfl_xor_sync(0xffffffffu, sum0, 2);
        sum1 += __shfl_xor_sync(0xffffffffu, sum1, 1);
        sum1 += __shfl_xor_sync(0xffffffffu, sum1, 2);
        lrow0 = lrow0 * corr0 + sum0;
        lrow1 = lrow1 * corr1 + sum1;

        #pragma unroll
        for (int nt = 0; nt < 8; nt++) {
            o[nt][0] *= corr0; o[nt][1] *= corr0;
            o[nt][2] *= corr1; o[nt][3] *= corr1;
        }

        // ---- P @ V: register-resident P (C-frag == A-frag), 2-pass ----
        #pragma unroll
        for (int ks2 = 0; ks2 < 8; ks2++) {
            uint32_t phi[4], plo[4];
            split_pack_h(s[2*ks2][0],     s[2*ks2][1],     phi[0], plo[0]);
            split_pack_h(s[2*ks2][2],     s[2*ks2][3],     phi[1], plo[1]);
            split_pack_h(s[2*ks2 + 1][0], s[2*ks2 + 1][1], phi[2], plo[2]);
            split_pack_h(s[2*ks2 + 1][2], s[2*ks2 + 1][3], phi[3], plo[3]);
            const int kkh = ks2 * 16;
            #pragma unroll
            for (int nt = 0; nt < 8; nt++) {
                uint32_t vh[2];
                vh[0] = *(const uint32_t*)&Vt[(nt * 8 + g) * VSTRH + kkh + 2 * tg];
                vh[1] = *(const uint32_t*)&Vt[(nt * 8 + g) * VSTRH + kkh + 2 * tg + 8];
                mma16(o[nt], phi, vh);
                mma16(o[nt], plo, vh);
            }
        }
    }

    // ---- epilogue: normalize, split fp16 hi/lo for the O-GEMM ----
    const float inv0 = 1.0f / lrow0;
    const float inv1 = 1.0f / lrow1;
    const int q0 = qblk * 128 + w * 16 + g;
    #pragma unroll
    for (int nt = 0; nt < 8; nt++) {
        uint32_t h0, l0, h1, l1;
        split_pack_h(o[nt][0] * inv0, o[nt][1] * inv0, h0, l0);
        split_pack_h(o[nt][2] * inv1, o[nt][3] * inv1, h1, l1);
        const size_t a0 = gidx(q0) + nt * 8 + 2 * tg;
        const size_t a1 = gidx(q0 + 8) + nt * 8 + 2 * tg;
        *(uint32_t*)(Ohi + a0) = h0;
        *(uint32_t*)(Olo + a0) = l0;
        *(uint32_t*)(Ohi + a1) = h1;
        *(uint32_t*)(Olo + a1) = l1;
    }
}

// ---------------------------------------------------------------------------
extern "C" void kernel_launch(void* const* d_in, const int* in_sizes, int n_in,
                              void* d_out, int out_size)
{
    (void)in_sizes; (void)n_in; (void)out_size;
    const float* query = (const float*)d_in[0];
    const float* key   = (const float*)d_in[1];
    const float* value = (const float*)d_in[2];
    const float* Wq    = (const float*)d_in[3];
    const float* bq    = (const float*)d_in[4];
    const float* Wk    = (const float*)d_in[5];
    const float* bk    = (const float*)d_in[6];
    const float* Wv    = (const float*)d_in[7];
    const float* bv    = (const float*)d_in[8];
    const float* Wo    = (const float*)d_in[9];
    const float* bo    = (const float*)d_in[10];
    float* out = (float*)d_out;

    float *qp;
    __half *kh, *vt, *ahi, *alo, *wq, *wk, *wv, *wo, *xhi, *xlo;
    cudaGetSymbolAddress((void**)&qp,  g_q);
    cudaGetSymbolAddress((void**)&kh,  g_kh);
    cudaGetSymbolAddress((void**)&vt,  g_vt);
    cudaGetSymbolAddress((void**)&ahi, g_ahi);
    cudaGetSymbolAddress((void**)&alo, g_alo);
    cudaGetSymbolAddress((void**)&wq,  g_wq);
    cudaGetSymbolAddress((void**)&wk,  g_wk);
    cudaGetSymbolAddress((void**)&wv,  g_wv);
    cudaGetSymbolAddress((void**)&wo,  g_wo);
    cudaGetSymbolAddress((void**)&xhi, g_xhi);
    cudaGetSymbolAddress((void**)&xlo, g_xlo);

    cudaFuncSetAttribute(gemm_fp16_kernel<0>,
                         cudaFuncAttributeMaxDynamicSharedMemorySize, G_SMEM_B);
    cudaFuncSetAttribute(gemm_fp16_kernel<2>,
                         cudaFuncAttributeMaxDynamicSharedMemorySize, G_SMEM_B);
    cudaFuncSetAttribute(gemm_fp16_kernel<3>,
                         cudaFuncAttributeMaxDynamicSharedMemorySize, G_SMEM_B);
    cudaFuncSetAttribute(attn_tc_kernel,
                         cudaFuncAttributeMaxDynamicSharedMemorySize, A_TOTAL);

    // Pre-convert weights to fp16 (one launch)
    RoundArgs ra;
    ra.w[0] = Wq; ra.w[1] = Wk; ra.w[2] = Wv; ra.w[3] = Wo;
    ra.o[0] = wq; ra.o[1] = wk; ra.o[2] = wv; ra.o[3] = wo;
    {
        dim3 rgrid(DMODEL * DMODEL / (256 * 4), 1, 4);
        round_w_kernel<<<rgrid, 256>>>(ra);
    }
    // Pre-split activations to fp16 hi/lo (one launch)
    SplitArgs sa;
    sa.x[0] = query; sa.x[1] = key; sa.x[2] = value;
    sa.hi[0] = xhi;             sa.lo[0] = xlo;
    sa.hi[1] = xhi + NELEM;     sa.lo[1] = xlo + NELEM;
    sa.hi[2] = xhi + 2 * NELEM; sa.lo[2] = xlo + 2 * NELEM;
    {
        dim3 sgrid(NELEM / (256 * 4), 1, 3);
        split_x_kernel<<<sgrid, 256>>>(sa);
    }

    // Projections
    dim3 ggrid(DMODEL / 128, MROWS / 128);   // (8, 32)
    gemm_fp16_kernel<0><<<ggrid, 256, G_SMEM_B>>>(
        xhi,             xlo,             wq, bq, qp, MROWS, DMODEL, DMODEL);
    gemm_fp16_kernel<2><<<ggrid, 256, G_SMEM_B>>>(
        xhi + NELEM,     xlo + NELEM,     wk, bk, kh, MROWS, DMODEL, DMODEL);
    gemm_fp16_kernel<3><<<ggrid, 256, G_SMEM_B>>>(
        xhi + 2 * NELEM, xlo + 2 * NELEM, wv, bv, vt, MROWS, DMODEL, DMODEL);

    // Attention: 128 q-rows per CTA, 128-key tiles, register-P fp16 path
    dim3 agrid(S_LEN / 128, NHEAD * BATCH);  // (16, 32)
    attn_tc_kernel<<<agrid, 256, A_TOTAL>>>(qp, kh, vt, ahi, alo);

    // Output projection (consumes attention's fp16 hi/lo split)
    gemm_fp16_kernel<0><<<ggrid, 256, G_SMEM_B>>>(
        ahi, alo, wo, bo, out, MROWS, DMODEL, DMODEL);
}

// round 17
// speedup vs baseline: 1.0263x; 1.0263x over previous
#include <cuda_runtime.h>
#include <cuda_fp16.h>
#include <math.h>
#include <stdint.h>

// Problem constants (fixed by the reference)
#define S_LEN   2048
#define BATCH   2
#define DMODEL  1024
#define NHEAD   16
#define DHEAD   64
#define MROWS   (S_LEN * BATCH)
#define NELEM   (S_LEN * BATCH * DMODEL)   // 4M

// Scratch (no allocation allowed)
__device__ float  g_q[NELEM];                       // Q projected, f32
__device__ __align__(16) __half g_kh[NELEM];        // K projected, fp16
__device__ __align__(16) __half g_vt[NELEM];        // V projected, fp16 TRANSPOSED [(h,b)][d][s]
__device__ __align__(16) __half g_ahi[NELEM];       // attention out hi (fp16)
__device__ __align__(16) __half g_alo[NELEM];       // attention out lo (fp16)
// fp16 weights
__device__ __align__(16) __half g_wq[DMODEL * DMODEL];
__device__ __align__(16) __half g_wk[DMODEL * DMODEL];
__device__ __align__(16) __half g_wv[DMODEL * DMODEL];
__device__ __align__(16) __half g_wo[DMODEL * DMODEL];
// fp16 hi/lo split activations
__device__ __align__(16) __half g_xhi[3 * NELEM];
__device__ __align__(16) __half g_xlo[3 * NELEM];

// ---------------------------------------------------------------------------
// Helpers
// ---------------------------------------------------------------------------
// fp16 m16n8k16, fp32 accumulate
__device__ __forceinline__ void mma16(float c[4], const uint32_t a[4],
                                      const uint32_t b[2]) {
    asm volatile(
        "mma.sync.aligned.m16n8k16.row.col.f32.f16.f16.f32 "
        "{%0,%1,%2,%3}, {%4,%5,%6,%7}, {%8,%9}, {%0,%1,%2,%3};\n"
        : "+f"(c[0]), "+f"(c[1]), "+f"(c[2]), "+f"(c[3])
        : "r"(a[0]), "r"(a[1]), "r"(a[2]), "r"(a[3]),
          "r"(b[0]), "r"(b[1]));
}

__device__ __forceinline__ void cp_async16(uint32_t smem_addr, const void* gptr) {
    asm volatile("cp.async.cg.shared.global [%0], [%1], 16;\n"
                 :: "r"(smem_addr), "l"(gptr));
}
__device__ __forceinline__ void cp_commit() {
    asm volatile("cp.async.commit_group;\n");
}
__device__ __forceinline__ void cp_wait1() {
    asm volatile("cp.async.wait_group 1;\n");
}
__device__ __forceinline__ uint32_t smem_u32(const void* p) {
    return (uint32_t)__cvta_generic_to_shared(p);
}

__device__ __forceinline__ uint32_t pack2h(__half a, __half b) {
    return (uint32_t)__half_as_ushort(a) | ((uint32_t)__half_as_ushort(b) << 16);
}

// fp16 hi/lo split of two floats -> packed half2 hi and lo
__device__ __forceinline__ void split_pack_h(float x0, float x1,
                                             uint32_t& hi, uint32_t& lo) {
    __half h0 = __float2half_rn(x0);
    __half h1 = __float2half_rn(x1);
    __half l0 = __float2half_rn(x0 - __half2float(h0));
    __half l1 = __float2half_rn(x1 - __half2float(h1));
    hi = pack2h(h0, h1);
    lo = pack2h(l0, l1);
}

// ---------------------------------------------------------------------------
// Weight pre-conversion to fp16 (4 matrices, one launch)
// ---------------------------------------------------------------------------
struct RoundArgs { const float* w[4]; __half* o[4]; };

__global__ void __launch_bounds__(256)
round_w_kernel(RoundArgs a)
{
    const int z = blockIdx.z;
    const int i = (blockIdx.x * 256 + threadIdx.x) * 4;
    float4 v = *(const float4*)(a.w[z] + i);
    uint2 h;
    h.x = pack2h(__float2half_rn(v.x), __float2half_rn(v.y));
    h.y = pack2h(__float2half_rn(v.z), __float2half_rn(v.w));
    *(uint2*)(a.o[z] + i) = h;
}

// Activation pre-split to fp16 hi/lo (3 tensors, one launch)
struct SplitArgs { const float* x[3]; __half* hi[3]; __half* lo[3]; };

__global__ void __launch_bounds__(256)
split_x_kernel(SplitArgs a)
{
    const int z = blockIdx.z;
    const int i = (blockIdx.x * 256 + threadIdx.x) * 4;
    float4 v = *(const float4*)(a.x[z] + i);
    uint2 h, l;
    split_pack_h(v.x, v.y, h.x, l.x);
    split_pack_h(v.z, v.w, h.y, l.y);
    *(uint2*)(a.hi[z] + i) = h;
    *(uint2*)(a.lo[z] + i) = l;
}

// ---------------------------------------------------------------------------
// fp16 projection GEMM (R15 structure): Y = (Xhi+Xlo) @ W^T + bias, 2-pass k16.
// 2-stage cp.async pipeline. mma issue REORDERED: all hi-pass mmas, then all
// lo-pass mmas (per-accumulator order unchanged -> bit-identical).
// MODE: 0 = f32 out, 2 = fp16 out, 3 = fp16 TRANSPOSED out (for V).
// ---------------------------------------------------------------------------
#define GROWB 80
#define G_TILE_B (128 * GROWB)
#define G_SMEM_B (6 * G_TILE_B)        // 61440

template<int MODE>
__global__ void __launch_bounds__(256, 2)
gemm_fp16_kernel(const __half* __restrict__ Xhi, const __half* __restrict__ Xlo,
                 const __half* __restrict__ W, const float* __restrict__ bias,
                 void* __restrict__ Yv, int M, int N, int K)
{
    extern __shared__ char smc[];
    const int tid  = threadIdx.x;
    const int lane = tid & 31;
    const int w    = tid >> 5;
    const int wm   = w >> 2;
    const int wn   = w & 3;
    const int m0   = blockIdx.y * 128;
    const int n0   = blockIdx.x * 128;
    const int g    = lane >> 2;
    const int tg   = lane & 3;

    float c[4][4][4] = {};
    const uint32_t sbase = smem_u32(smc);

    auto issue_tile = [&](int k0, int buf) {
        #pragma unroll
        for (int i = 0; i < 2; i++) {
            const int ch  = i * 256 + tid;
            const int row = ch >> 2;
            const int seg = ch & 3;
            const uint32_t soff = (uint32_t)(row * GROWB + seg * 16);
            const size_t gx = (size_t)(m0 + row) * K + k0 + seg * 8;
            cp_async16(sbase + (uint32_t)buf * G_TILE_B + soff,  Xhi + gx);
            cp_async16(sbase + (2u + buf) * G_TILE_B + soff,     Xlo + gx);
            cp_async16(sbase + (4u + buf) * G_TILE_B + soff,
                       W + (size_t)(n0 + row) * K + k0 + seg * 8);
        }
    };

    issue_tile(0, 0);
    cp_commit();

    const int NT = K / 32;
    for (int kt = 0; kt < NT; kt++) {
        if (kt + 1 < NT) issue_tile((kt + 1) * 32, (kt + 1) & 1);
        cp_commit();
        cp_wait1();
        __syncthreads();

        const char* Ah = smc + (kt & 1) * G_TILE_B + (wm * 64) * GROWB;
        const char* Al = Ah + 2 * G_TILE_B;
        const char* Bt = smc + (4 + (kt & 1)) * G_TILE_B + (wn * 32) * GROWB;

        #pragma unroll
        for (int ks = 0; ks < 2; ks++) {
            const int kb = ks * 32 + tg * 4;
            uint32_t ahi[4][4], alo[4][4];
            #pragma unroll
            for (int mt = 0; mt < 4; mt++) {
                const char* ph = Ah + (mt * 16 + g) * GROWB + kb;
                const char* pl = Al + (mt * 16 + g) * GROWB + kb;
                ahi[mt][0] = *(const uint32_t*)(ph);
                ahi[mt][1] = *(const uint32_t*)(ph + 8 * GROWB);
                ahi[mt][2] = *(const uint32_t*)(ph + 16);
                ahi[mt][3] = *(const uint32_t*)(ph + 8 * GROWB + 16);
                alo[mt][0] = *(const uint32_t*)(pl);
                alo[mt][1] = *(const uint32_t*)(pl + 8 * GROWB);
                alo[mt][2] = *(const uint32_t*)(pl + 16);
                alo[mt][3] = *(const uint32_t*)(pl + 8 * GROWB + 16);
            }
            uint32_t bh[4][2];
            #pragma unroll
            for (int nt = 0; nt < 4; nt++) {
                const char* pb = Bt + (nt * 8 + g) * GROWB + kb;
                bh[nt][0] = *(const uint32_t*)(pb);
                bh[nt][1] = *(const uint32_t*)(pb + 16);
            }
            // hi pass: 16 independent mmas
            #pragma unroll
            for (int mt = 0; mt < 4; mt++)
                #pragma unroll
                for (int nt = 0; nt < 4; nt++)
                    mma16(c[mt][nt], ahi[mt], bh[nt]);
            // lo pass: 16 independent mmas (each depends on its hi, 15 apart)
            #pragma unroll
            for (int mt = 0; mt < 4; mt++)
                #pragma unroll
                for (int nt = 0; nt < 4; nt++)
                    mma16(c[mt][nt], alo[mt], bh[nt]);
        }
        __syncthreads();
    }

    #pragma unroll
    for (int mt = 0; mt < 4; mt++) {
        const int r0 = m0 + wm * 64 + mt * 16 + g;
        #pragma unroll
        for (int nt = 0; nt < 4; nt++) {
            const int cb = n0 + wn * 32 + nt * 8 + tg * 2;
            float2 bv = *(const float2*)(bias + cb);
            float2 v0, v1;
            v0.x = c[mt][nt][0] + bv.x; v0.y = c[mt][nt][1] + bv.y;
            v1.x = c[mt][nt][2] + bv.x; v1.y = c[mt][nt][3] + bv.y;
            if (MODE == 0) {
                *(float2*)((float*)Yv + (size_t)r0 * N + cb)       = v0;
                *(float2*)((float*)Yv + (size_t)(r0 + 8) * N + cb) = v1;
            } else if (MODE == 2) {
                uint32_t h0 = pack2h(__float2half_rn(v0.x), __float2half_rn(v0.y));
                uint32_t h1 = pack2h(__float2half_rn(v1.x), __float2half_rn(v1.y));
                *(uint32_t*)((__half*)Yv + (size_t)r0 * N + cb)       = h0;
                *(uint32_t*)((__half*)Yv + (size_t)(r0 + 8) * N + cb) = h1;
            } else {
                // MODE 3: transposed fp16 V:  Vt[(h*2+b)*64 + d][s]
                auto st = [&](int r, int cc, float v) {
                    const int s  = r >> 1;
                    const int bb = r & 1;
                    const int hh = cc >> 6;
                    const int d  = cc & 63;
                    ((__half*)Yv)[((size_t)((hh * 2 + bb) * 64 + d)) * S_LEN + s]
                        = __float2half_rn(v);
                };
                st(r0,     cb,     v0.x); st(r0,     cb + 1, v0.y);
                st(r0 + 8, cb,     v1.x); st(r0 + 8, cb + 1, v1.y);
            }
        }
    }
}

// ---------------------------------------------------------------------------
// Flash attention v7: R15 structure (2-stage, register-resident P), with
// mma issue reordered into hi-pass/lo-pass groups of 8 (bit-identical).
// ---------------------------------------------------------------------------
#define KROWB 144                       // K tile row: 64 halves + pad
#define A_KT  (128 * KROWB)             // 18432
#define VROWB 272                       // Vt tile row: 128 keys (fp16) + pad
#define VSTRH 136                       // Vt row stride in halves
#define A_VT  (64 * VROWB)              // 17408
#define A_K(buf) ((buf) * A_KT)
#define A_V(buf) (2 * A_KT + (buf) * A_VT)
#define A_TOTAL  (2 * A_KT + 2 * A_VT)  // 71680 (Q staged in same region first)

__global__ void __launch_bounds__(256)
attn_tc_kernel(const float* __restrict__ Q, const __half* __restrict__ Kp,
               const __half* __restrict__ Vtg,
               __half* __restrict__ Ohi, __half* __restrict__ Olo)
{
    extern __shared__ char smc[];
    const int tid  = threadIdx.x;
    const int lane = tid & 31;
    const int w    = tid >> 5;
    const int g    = lane >> 2;
    const int tg   = lane & 3;

    const int qblk = blockIdx.x;
    const int hb   = blockIdx.y;
    const int h    = hb >> 1;
    const int b    = hb & 1;
    const int hoff = h * DHEAD;

    const uint32_t sbase = smem_u32(smc);
    const __half* Vtp = Vtg + (size_t)(h * 2 + b) * 64 * S_LEN;

    auto gidx = [&](int row) -> size_t {
        return ((size_t)row * BATCH + b) * DMODEL + hoff;
    };

    // stage Q tile (128 x 64 f32) into smem (region reused by K/V after)
    {
        float* Qst = (float*)smc;
        #pragma unroll
        for (int i = 0; i < 8; i++) {
            const int ch  = i * 256 + tid;
            const int row = ch >> 4;
            const int seg = ch & 15;
            float4 v = *(const float4*)(Q + gidx(qblk * 128 + row) + seg * 4);
            *(float4*)&Qst[row * 132 + seg * 4] = v;
        }
    }
    __syncthreads();

    // persistent fp16 hi/lo Q fragments (4 k16-steps)
    uint32_t qhi[4][4], qlo[4][4];
    {
        const float* Qs = (const float*)smc + (w * 16) * 132;
        #pragma unroll
        for (int ks = 0; ks < 4; ks++) {
            const int kk = ks * 16;
            float2 q00 = *(const float2*)&Qs[g * 132 + kk + 2 * tg];
            float2 q10 = *(const float2*)&Qs[(g + 8) * 132 + kk + 2 * tg];
            float2 q01 = *(const float2*)&Qs[g * 132 + kk + 2 * tg + 8];
            float2 q11 = *(const float2*)&Qs[(g + 8) * 132 + kk + 2 * tg + 8];
            split_pack_h(q00.x, q00.y, qhi[ks][0], qlo[ks][0]);
            split_pack_h(q10.x, q10.y, qhi[ks][1], qlo[ks][1]);
            split_pack_h(q01.x, q01.y, qhi[ks][2], qlo[ks][2]);
            split_pack_h(q11.x, q11.y, qhi[ks][3], qlo[ks][3]);
        }
    }
    __syncthreads();   // Q staging fully consumed; K/V may overwrite

    // K (fp16, key-major) + Vt (fp16, dhead-major) tile loads
    auto issue_kv = [&](int kb, int buf) {
        #pragma unroll
        for (int i = 0; i < 4; i++) {            // K: 128 rows x 8 segs
            const int ch  = i * 256 + tid;
            const int row = ch >> 3;
            const int seg = ch & 7;
            cp_async16(sbase + (uint32_t)(A_K(buf) + row * KROWB + seg * 16),
                       Kp + gidx(kb + row) + seg * 8);
        }
        #pragma unroll
        for (int i = 0; i < 4; i++) {            // Vt: 64 rows x 16 segs
            const int ch  = i * 256 + tid;
            const int row = ch >> 4;             // 0..63 (dhead)
            const int seg = ch & 15;
            cp_async16(sbase + (uint32_t)(A_V(buf) + row * VROWB + seg * 16),
                       Vtp + (size_t)row * S_LEN + kb + seg * 8);
        }
    };

    issue_kv(0, 0);
    cp_commit();

    float o[8][4] = {};
    float mrow0 = -1e30f, mrow1 = -1e30f;
    float lrow0 = 0.0f,   lrow1 = 0.0f;
    const float scale = 0.125f;

    const int NKT = S_LEN / 128;   // 16 tiles
    for (int kt = 0; kt < NKT; kt++) {
        if (kt + 1 < NKT) issue_kv((kt + 1) * 128, (kt + 1) & 1);
        cp_commit();
        cp_wait1();
        __syncthreads();

        const char* Kt = smc + A_K(kt & 1);
        const __half* Vt = (const __half*)(smc + A_V(kt & 1));

        // ---- QK^T over 128 keys: fp16 k16, groups of 8 (hi-pass / lo-pass) ----
        float s[16][4] = {};
        #pragma unroll
        for (int ks = 0; ks < 4; ks++) {
            const int kb = ks * 32 + tg * 4;
            #pragma unroll
            for (int hf = 0; hf < 2; hf++) {
                uint32_t bh[8][2];
                #pragma unroll
                for (int j = 0; j < 8; j++) {
                    const char* pk = Kt + ((hf * 8 + j) * 8 + g) * KROWB + kb;
                    bh[j][0] = *(const uint32_t*)(pk);
                    bh[j][1] = *(const uint32_t*)(pk + 16);
                }
                #pragma unroll
                for (int j = 0; j < 8; j++)
                    mma16(s[hf * 8 + j], qhi[ks], bh[j]);
                #pragma unroll
                for (int j = 0; j < 8; j++)
                    mma16(s[hf * 8 + j], qlo[ks], bh[j]);
            }
        }

        // ---- online softmax (R10 numerics, unchanged) ----
        float mx0 = -1e30f, mx1 = -1e30f;
        #pragma unroll
        for (int nt = 0; nt < 16; nt++) {
            s[nt][0] *= scale; s[nt][1] *= scale;
            s[nt][2] *= scale; s[nt][3] *= scale;
            mx0 = fmaxf(mx0, fmaxf(s[nt][0], s[nt][1]));
            mx1 = fmaxf(mx1, fmaxf(s[nt][2], s[nt][3]));
        }
        mx0 = fmaxf(mx0, __shfl_xor_sync(0xffffffffu, mx0, 1));
        mx0 = fmaxf(mx0, __shfl_xor_sync(0xffffffffu, mx0, 2));
        mx1 = fmaxf(mx1, __shfl_xor_sync(0xffffffffu, mx1, 1));
        mx1 = fmaxf(mx1, __shfl_xor_sync(0xffffffffu, mx1, 2));

        const float mn0 = fmaxf(mrow0, mx0);
        const float mn1 = fmaxf(mrow1, mx1);
        const float corr0 = __expf(mrow0 - mn0);
        const float corr1 = __expf(mrow1 - mn1);
        mrow0 = mn0; mrow1 = mn1;

        float sum0 = 0.0f, sum1 = 0.0f;
        #pragma unroll
        for (int nt = 0; nt < 16; nt++) {
            s[nt][0] = __expf(s[nt][0] - mn0);
            s[nt][1] = __expf(s[nt][1] - mn0);
            s[nt][2] = __expf(s[nt][2] - mn1);
            s[nt][3] = __expf(s[nt][3] - mn1);
            sum0 += s[nt][0] + s[nt][1];
            sum1 += s[nt][2] + s[nt][3];
        }
        sum0 += __shfl_xor_sync(0xffffffffu, sum0, 1);
        sum0 += __shfl_xor_sync(0xffffffffu, sum0, 2);
        sum1 += __shfl_xor_sync(0xffffffffu, sum1, 1);
        sum1 += __shfl_xor_sync(0xffffffffu, sum1, 2);
        lrow0 = lrow0 * corr0 + sum0;
        lrow1 = lrow1 * corr1 + sum1;

        #pragma unroll
        for (int nt = 0; nt < 8; nt++) {
            o[nt][0] *= corr0; o[nt][1] *= corr0;
            o[nt][2] *= corr1; o[nt][3] *= corr1;
        }

        // ---- P @ V: register-resident P, hi-pass then lo-pass over 8 nt ----
        #pragma unroll
        for (int ks2 = 0; ks2 < 8; ks2++) {
            uint32_t phi[4], plo[4];
            split_pack_h(s[2*ks2][0],     s[2*ks2][1],     phi[0], plo[0]);
            split_pack_h(s[2*ks2][2],     s[2*ks2][3],     phi[1], plo[1]);
            split_pack_h(s[2*ks2 + 1][0], s[2*ks2 + 1][1], phi[2], plo[2]);
            split_pack_h(s[2*ks2 + 1][2], s[2*ks2 + 1][3], phi[3], plo[3]);
            const int kkh = ks2 * 16;
            uint32_t vh[8][2];
            #pragma unroll
            for (int nt = 0; nt < 8; nt++) {
                vh[nt][0] = *(const uint32_t*)&Vt[(nt * 8 + g) * VSTRH + kkh + 2 * tg];
                vh[nt][1] = *(const uint32_t*)&Vt[(nt * 8 + g) * VSTRH + kkh + 2 * tg + 8];
            }
            #pragma unroll
            for (int nt = 0; nt < 8; nt++)
                mma16(o[nt], phi, vh[nt]);
            #pragma unroll
            for (int nt = 0; nt < 8; nt++)
                mma16(o[nt], plo, vh[nt]);
        }
    }

    // ---- epilogue: normalize, split fp16 hi/lo for the O-GEMM ----
    const float inv0 = 1.0f / lrow0;
    const float inv1 = 1.0f / lrow1;
    const int q0 = qblk * 128 + w * 16 + g;
    #pragma unroll
    for (int nt = 0; nt < 8; nt++) {
        uint32_t h0, l0, h1, l1;
        split_pack_h(o[nt][0] * inv0, o[nt][1] * inv0, h0, l0);
        split_pack_h(o[nt][2] * inv1, o[nt][3] * inv1, h1, l1);
        const size_t a0 = gidx(q0) + nt * 8 + 2 * tg;
        const size_t a1 = gidx(q0 + 8) + nt * 8 + 2 * tg;
        *(uint32_t*)(Ohi + a0) = h0;
        *(uint32_t*)(Olo + a0) = l0;
        *(uint32_t*)(Ohi + a1) = h1;
        *(uint32_t*)(Olo + a1) = l1;
    }
}

// ---------------------------------------------------------------------------
extern "C" void kernel_launch(void* const* d_in, const int* in_sizes, int n_in,
                              void* d_out, int out_size)
{
    (void)in_sizes; (void)n_in; (void)out_size;
    const float* query = (const float*)d_in[0];
    const float* key   = (const float*)d_in[1];
    const float* value = (const float*)d_in[2];
    const float* Wq    = (const float*)d_in[3];
    const float* bq    = (const float*)d_in[4];
    const float* Wk    = (const float*)d_in[5];
    const float* bk    = (const float*)d_in[6];
    const float* Wv    = (const float*)d_in[7];
    const float* bv    = (const float*)d_in[8];
    const float* Wo    = (const float*)d_in[9];
    const float* bo    = (const float*)d_in[10];
    float* out = (float*)d_out;

    float *qp;
    __half *kh, *vt, *ahi, *alo, *wq, *wk, *wv, *wo, *xhi, *xlo;
    cudaGetSymbolAddress((void**)&qp,  g_q);
    cudaGetSymbolAddress((void**)&kh,  g_kh);
    cudaGetSymbolAddress((void**)&vt,  g_vt);
    cudaGetSymbolAddress((void**)&ahi, g_ahi);
    cudaGetSymbolAddress((void**)&alo, g_alo);
    cudaGetSymbolAddress((void**)&wq,  g_wq);
    cudaGetSymbolAddress((void**)&wk,  g_wk);
    cudaGetSymbolAddress((void**)&wv,  g_wv);
    cudaGetSymbolAddress((void**)&wo,  g_wo);
    cudaGetSymbolAddress((void**)&xhi, g_xhi);
    cudaGetSymbolAddress((void**)&xlo, g_xlo);

    cudaFuncSetAttribute(gemm_fp16_kernel<0>,
                         cudaFuncAttributeMaxDynamicSharedMemorySize, G_SMEM_B);
    cudaFuncSetAttribute(gemm_fp16_kernel<2>,
                         cudaFuncAttributeMaxDynamicSharedMemorySize, G_SMEM_B);
    cudaFuncSetAttribute(gemm_fp16_kernel<3>,
                         cudaFuncAttributeMaxDynamicSharedMemorySize, G_SMEM_B);
    cudaFuncSetAttribute(attn_tc_kernel,
                         cudaFuncAttributeMaxDynamicSharedMemorySize, A_TOTAL);

    // Pre-convert weights to fp16 (one launch)
    RoundArgs ra;
    ra.w[0] = Wq; ra.w[1] = Wk; ra.w[2] = Wv; ra.w[3] = Wo;
    ra.o[0] = wq; ra.o[1] = wk; ra.o[2] = wv; ra.o[3] = wo;
    {
        dim3 rgrid(DMODEL * DMODEL / (256 * 4), 1, 4);
        round_w_kernel<<<rgrid, 256>>>(ra);
    }
    // Pre-split activations to fp16 hi/lo (one launch)
    SplitArgs sa;
    sa.x[0] = query; sa.x[1] = key; sa.x[2] = value;
    sa.hi[0] = xhi;             sa.lo[0] = xlo;
    sa.hi[1] = xhi + NELEM;     sa.lo[1] = xlo + NELEM;
    sa.hi[2] = xhi + 2 * NELEM; sa.lo[2] = xlo + 2 * NELEM;
    {
        dim3 sgrid(NELEM / (256 * 4), 1, 3);
        split_x_kernel<<<sgrid, 256>>>(sa);
    }

    // Projections
    dim3 ggrid(DMODEL / 128, MROWS / 128);   // (8, 32)
    gemm_fp16_kernel<0><<<ggrid, 256, G_SMEM_B>>>(
        xhi,             xlo,             wq, bq, qp, MROWS, DMODEL, DMODEL);
    gemm_fp16_kernel<2><<<ggrid, 256, G_SMEM_B>>>(
        xhi + NELEM,     xlo + NELEM,     wk, bk, kh, MROWS, DMODEL, DMODEL);
    gemm_fp16_kernel<3><<<ggrid, 256, G_SMEM_B>>>(
        xhi + 2 * NELEM, xlo + 2 * NELEM, wv, bv, vt, MROWS, DMODEL, DMODEL);

    // Attention: 128 q-rows per CTA, 128-key tiles, register-P fp16 path
    dim3 agrid(S_LEN / 128, NHEAD * BATCH);  // (16, 32)
    attn_tc_kernel<<<agrid, 256, A_TOTAL>>>(qp, kh, vt, ahi, alo);

    // Output projection (consumes attention's fp16 hi/lo split)
    gemm_fp16_kernel<0><<<ggrid, 256, G_SMEM_B>>>(
        ahi, alo, wo, bo, out, MROWS, DMODEL, DMODEL);
}